// round 8
// baseline (speedup 1.0000x reference)
#include <cuda_runtime.h>
#include <cstdint>

#define BB 256
#define TT 256
#define CC 1024
#define LL 64
#define SS 129          // 2L+1
#define GW 72           // padded gather width: 64 labels + blank@64, pad to 72
#define CH 16           // time-rows per smem chunk
#define NCHUNK (TT / CH)
#define ABLK 64         // consumer (alpha) blocks: 4 warps = 4 batches each
#define RBLK 380        // producer (reduce) blocks: 4 warps each
#define RWARPS (RBLK * 4)
#define NEGV (-1e30f)
#define EPSF 1e-7f
#define LN2F 0.69314718055994530942f

// scratch (no allocation allowed -> __device__ globals)
__device__ float g_buf[(size_t)BB * TT * GW];   // emit table, LOG2 domain
__device__ int   done_ctr[NCHUNK];              // rows completed per t-chunk

__device__ __forceinline__ float fexp2(float x) {
    float y; asm("ex2.approx.ftz.f32 %0, %1;" : "=f"(y) : "f"(x)); return y;
}
__device__ __forceinline__ float flog2(float x) {
    float y; asm("lg2.approx.ftz.f32 %0, %1;" : "=f"(y) : "f"(x)); return y;
}

__device__ __forceinline__ bool detect_i64(const int* yt, int lane) {
    return __all_sync(0xffffffffu, yt[2 * lane + 1] == 0);
}
__device__ __forceinline__ int load_lab(const int* yt, bool is64, int idx) {
    int v = is64 ? yt[2 * idx] : yt[idx];
    return min(max(v, 0), CC - 1);              // clamp: safety net
}

__global__ void k_zero() {
    if (threadIdx.x < NCHUNK) done_ctr[threadIdx.x] = 0;
}

// ---------------------------------------------------------------------------
// producer side: one warp per (b,t) row, rows walked t-major so early time
// chunks (for ALL batches) complete first.
// log_softmax(log(y+EPS)) = log(y+EPS) - log(sum(y+EPS)) -> one plain sum.
// ---------------------------------------------------------------------------
__device__ __forceinline__ void produce_rows(const float* __restrict__ yp,
                                             const int*   __restrict__ yt,
                                             int gw, int lane) {
    bool is64 = detect_i64(yt, lane);
    for (int r = gw; r < BB * TT; r += RWARPS) {
        int t = r >> 8;                         // t-major streaming order
        int b = r & (BB - 1);

        const float*  row  = yp + ((size_t)b * TT + t) * CC;
        const float4* row4 = (const float4*)row;

        float s = 0.f;
        #pragma unroll
        for (int k = 0; k < 8; ++k) {           // 8 coalesced float4 per lane
            float4 v = row4[lane + 32 * k];
            s += (v.x + v.y) + (v.z + v.w);
        }
        #pragma unroll
        for (int o = 16; o; o >>= 1) s += __shfl_xor_sync(0xffffffffu, s, o);

        float l2Z = flog2(s + (float)CC * EPSF);

        float* go = g_buf + ((size_t)b * TT + t) * GW;
        #pragma unroll
        for (int q = 0; q < 2; ++q) {
            int j   = lane + 32 * q;
            int lab = load_lab(yt, is64, b * LL + j);
            go[j]   = flog2(row[lab] + EPSF) - l2Z;     // L1 hit: row just read
        }
        if (lane == 0)
            go[64] = flog2(row[CC - 1] + EPSF) - l2Z;   // blank

        __syncwarp();                            // all lanes' stores ordered
        __threadfence();                         // release
        if (lane == 0) atomicAdd(&done_ctr[t >> 4], 1);
    }
}

// ---------------------------------------------------------------------------
// consumer side: alpha recursion, LOG2 domain.  One warp per batch, 5 states
// per thread, 2 shuffles per step, cp.async double-buffered smem staging.
// Spin-waits (acquire) on done_ctr[c] before streaming chunk c.
// ---------------------------------------------------------------------------
__device__ __forceinline__ float stepf(float a1, float a2, float a3, float e) {
    float mm = fmaxf(a1, a2);
    float mx = fmaxf(mm, a3);
    float u  = fminf(a1, a2) - mx;
    float v  = fminf(mm, a3) - mx;
    float t  = 1.0f + fexp2(u) + fexp2(v);
    return mx + flog2(t) + e;
}

__device__ __forceinline__ void wait_ready(int c, int lane) {
    if (lane == 0) {
        volatile int* p = &done_ctr[c];
        while (*p < CH * BB) __nanosleep(64);
    }
    __syncwarp();
    __threadfence();                             // acquire
}

__device__ __forceinline__ void issue_chunk(const float4* gsrc,
                                            unsigned int sdst, int lane) {
    #pragma unroll
    for (int k = 0; k < (CH * GW) / (4 * 32); ++k) {   // 9 iters
        int i4 = lane + 32 * k;
        asm volatile("cp.async.ca.shared.global [%0], [%1], 16;\n"
                     :: "r"(sdst + 16u * i4), "l"(gsrc + i4));
    }
    asm volatile("cp.async.commit_group;\n" ::: "memory");
}
__device__ __forceinline__ void wait_cp() {
    asm volatile("cp.async.wait_group 0;\n" ::: "memory");
    __syncwarp();
}

__global__ void __launch_bounds__(128, 4)
k_fused(const float* __restrict__ yp, const int* __restrict__ yt,
        float* __restrict__ out) {
    __shared__ __align__(16) float sm[4][2][CH * GW];  // 36,864 B

    int w    = threadIdx.x >> 5;
    int lane = threadIdx.x & 31;

    if (blockIdx.x >= ABLK) {                   // ---------- producer role
        int gw = (blockIdx.x - ABLK) * 4 + w;
        produce_rows(yp, yt, gw, lane);
        return;
    }

    // ---------- consumer role: batch b per warp
    int b = blockIdx.x * 4 + w;
    bool is64 = detect_i64(yt, lane);

    int  eidx[5];
    bool valid[5], skip[5];
    #pragma unroll
    for (int i = 0; i < 5; ++i) {
        int s    = 5 * lane + i;
        valid[i] = (s < SS);
        bool odd = (s & 1);
        eidx[i]  = odd ? ((s - 1) >> 1) : 64;
        skip[i]  = false;
        if (valid[i] && odd && s >= 3) {        // pos>=2 and label state
            int j = (s - 1) >> 1;               // j >= 1 here
            skip[i] = (load_lab(yt, is64, b * LL + j) !=
                       load_lab(yt, is64, b * LL + j - 1));
        }
    }

    const float4* gb4 = (const float4*)(g_buf + (size_t)b * TT * GW);
    unsigned int sbase[2] = {
        (unsigned int)__cvta_generic_to_shared(&sm[w][0][0]),
        (unsigned int)__cvta_generic_to_shared(&sm[w][1][0])
    };

    wait_ready(0, lane);
    issue_chunk(gb4, sbase[0], lane);
    wait_cp();

    float a[5];
    {   // t = 0 init from smem row 0: only states 0,1 live
        const float* s0 = &sm[w][0][0];
        #pragma unroll
        for (int i = 0; i < 5; ++i) {
            int s = 5 * lane + i;
            a[i]  = (s < 2) ? s0[eidx[i]] : NEGV;
        }
    }

    #pragma unroll 1
    for (int c = 0; c < NCHUNK; ++c) {
        if (c + 1 < NCHUNK) {                   // stream next chunk while computing
            wait_ready(c + 1, lane);
            issue_chunk(gb4 + (size_t)(c + 1) * (CH * GW / 4),
                        sbase[(c + 1) & 1], lane);
        }

        const float* sbuf = &sm[w][c & 1][0];
        int r0 = (c == 0) ? 1 : 0;              // t=0 consumed by init

        #pragma unroll
        for (int r = 0; r < CH; ++r) {
            if (r < r0) continue;
            const float* srow = sbuf + r * GW;
            float ec[5];
            #pragma unroll
            for (int i = 0; i < 5; ++i) ec[i] = valid[i] ? srow[eidx[i]] : NEGV;

            float p4 = __shfl_up_sync(0xffffffffu, a[4], 1);   // state 5*lane-1
            float p3 = __shfl_up_sync(0xffffffffu, a[3], 1);   // state 5*lane-2
            if (lane == 0) { p4 = NEGV; p3 = NEGV; }

            float n0 = stepf(a[0], p4,   skip[0] ? p3   : NEGV, ec[0]);
            float n1 = stepf(a[1], a[0], skip[1] ? p4   : NEGV, ec[1]);
            float n2 = stepf(a[2], a[1], skip[2] ? a[0] : NEGV, ec[2]);
            float n3 = stepf(a[3], a[2], skip[3] ? a[1] : NEGV, ec[3]);
            float n4 = stepf(a[4], a[3], skip[4] ? a[2] : NEGV, ec[4]);
            a[0] = n0; a[1] = n1; a[2] = n2; a[3] = n3; a[4] = n4;
        }

        if (c + 1 < NCHUNK) wait_cp();          // next buffer ready
    }

    // states 127 (i=2) and 128 (i=3) live in lane 25; convert log2 -> ln
    if (lane == 25) {
        float x = a[2], y = a[3];
        float m = fmaxf(x, y);
        float r = m + flog2(1.0f + fexp2(fminf(x, y) - m));
        out[b] = -r * LN2F;
    }
}

// ---------------------------------------------------------------------------
extern "C" void kernel_launch(void* const* d_in, const int* in_sizes, int n_in,
                              void* d_out, int out_size) {
    // y_pred is by far the larger buffer; robust to metadata ordering.
    const float* yp;
    const int*   yt;
    if (in_sizes[0] > in_sizes[1]) {
        yp = (const float*)d_in[0];
        yt = (const int*)d_in[1];
    } else {
        yp = (const float*)d_in[1];
        yt = (const int*)d_in[0];
    }
    float* out = (float*)d_out;

    k_zero<<<1, 32>>>();                         // reset chunk counters
    k_fused<<<ABLK + RBLK, 128>>>(yp, yt, out);  // producers + consumers
}

// round 9
// speedup vs baseline: 2.2420x; 2.2420x over previous
#include <cuda_runtime.h>
#include <cstdint>

#define BB 256
#define TT 256
#define CC 1024
#define LL 64
#define SS 129          // 2L+1
#define GW 72           // padded gather width: 64 labels + blank@64, pad to 72
#define CH 16           // time-rows per smem chunk
#define NCHUNK (TT / CH)
#define EPSF 1e-7f
#define LN2F 0.69314718055994530942f

// scratch (no allocation allowed -> __device__ global)
__device__ float g_buf[(size_t)BB * TT * GW];   // emit table, LINEAR domain

__device__ __forceinline__ float fexp2(float x) {
    float y; asm("ex2.approx.ftz.f32 %0, %1;" : "=f"(y) : "f"(x)); return y;
}
__device__ __forceinline__ float flog2(float x) {
    float y; asm("lg2.approx.ftz.f32 %0, %1;" : "=f"(y) : "f"(x)); return y;
}

// int64-vs-int32 label dtype detection, one load + ballot per warp.
__device__ __forceinline__ bool detect_i64(const int* yt, int lane) {
    return __all_sync(0xffffffffu, yt[2 * lane + 1] == 0);
}
__device__ __forceinline__ int load_lab(const int* yt, bool is64, int idx) {
    int v = is64 ? yt[2 * idx] : yt[idx];
    return min(max(v, 0), CC - 1);              // clamp: safety net
}

// ---------------------------------------------------------------------------
// Kernel 1: per (b,t) row.  softmax(log(y+EPS)) = (y+EPS)/sum(y+EPS) -> one
// plain sum + one divide.  One warp per row; gather the 65 reachable classes
// as LINEAR probabilities (no logs at all).
// ---------------------------------------------------------------------------
__global__ void k_reduce_gather(const float* __restrict__ yp,
                                const int*   __restrict__ yt) {
    int warp = (blockIdx.x * blockDim.x + threadIdx.x) >> 5;
    int lane = threadIdx.x & 31;
    if (warp >= BB * TT) return;
    int b = warp >> 8;                          // row-major (B,T,C)

    bool is64 = detect_i64(yt, lane);

    const float*  row  = yp + (size_t)warp * CC;
    const float4* row4 = (const float4*)row;

    float s = 0.f;
    #pragma unroll
    for (int k = 0; k < 8; ++k) {               // 8 coalesced float4 per lane
        float4 v = row4[lane + 32 * k];
        s += (v.x + v.y) + (v.z + v.w);
    }
    #pragma unroll
    for (int o = 16; o; o >>= 1) s += __shfl_xor_sync(0xffffffffu, s, o);

    float invZ = 1.0f / (s + (float)CC * EPSF);

    float* go = g_buf + (size_t)warp * GW;
    #pragma unroll
    for (int r = 0; r < 2; ++r) {
        int j   = lane + 32 * r;
        int lab = load_lab(yt, is64, b * LL + j);
        go[j]   = (row[lab] + EPSF) * invZ;          // L1 hit: row just read
    }
    if (lane == 0)
        go[64] = (row[CC - 1] + EPSF) * invZ;        // blank
}

// ---------------------------------------------------------------------------
// Kernel 2: alpha recursion in LINEAR domain: a_new = (a1 + a2 + skip*a3) * p.
// Pure FMA-pipe inner loop (no MUFU).  Renormalize by the warp-max's power of
// two every 8 steps (bit-twiddled 2^-k scale; exponent accumulated).
// One warp per batch, 5 states/thread, 2 shuffles/step, cp.async staging.
// ---------------------------------------------------------------------------
__device__ __forceinline__ void issue_chunk(const float4* gsrc,
                                            unsigned int sdst, int lane) {
    #pragma unroll
    for (int k = 0; k < (CH * GW) / (4 * 32); ++k) {   // 9 iters
        int i4 = lane + 32 * k;
        asm volatile("cp.async.ca.shared.global [%0], [%1], 16;\n"
                     :: "r"(sdst + 16u * i4), "l"(gsrc + i4));
    }
    asm volatile("cp.async.commit_group;\n" ::: "memory");
}
__device__ __forceinline__ void wait_cp() {
    asm volatile("cp.async.wait_group 0;\n" ::: "memory");
    __syncwarp();
}

__global__ void __launch_bounds__(128, 1)
k_alpha(const int* __restrict__ yt, float* __restrict__ out) {
    __shared__ __align__(16) float sm[4][2][CH * GW];  // 36,864 B

    int w    = threadIdx.x >> 5;
    int b    = blockIdx.x * 4 + w;
    int lane = threadIdx.x & 31;
    if (b >= BB) return;

    bool is64 = detect_i64(yt, lane);

    int   eidx[5];
    bool  valid[5];
    float skipm[5];
    #pragma unroll
    for (int i = 0; i < 5; ++i) {
        int s    = 5 * lane + i;
        valid[i] = (s < SS);
        bool odd = (s & 1);
        eidx[i]  = odd ? ((s - 1) >> 1) : 64;
        skipm[i] = 0.0f;
        if (valid[i] && odd && s >= 3) {        // pos>=2 and label state
            int j = (s - 1) >> 1;               // j >= 1 here
            skipm[i] = (load_lab(yt, is64, b * LL + j) !=
                        load_lab(yt, is64, b * LL + j - 1)) ? 1.0f : 0.0f;
        }
    }

    const float4* gb4 = (const float4*)(g_buf + (size_t)b * TT * GW);
    unsigned int sbase[2] = {
        (unsigned int)__cvta_generic_to_shared(&sm[w][0][0]),
        (unsigned int)__cvta_generic_to_shared(&sm[w][1][0])
    };

    // preload chunk 0 (rows 0..15)
    issue_chunk(gb4, sbase[0], lane);
    wait_cp();

    float a[5];
    {   // t = 0 init: only states 0,1 live (linear probability)
        const float* s0 = &sm[w][0][0];
        #pragma unroll
        for (int i = 0; i < 5; ++i) {
            int s = 5 * lane + i;
            a[i]  = (s < 2) ? s0[eidx[i]] : 0.0f;
        }
    }
    float acc = 0.0f;                           // accumulated log2 scale

    #pragma unroll 1
    for (int c = 0; c < NCHUNK; ++c) {
        if (c + 1 < NCHUNK)                     // stream next chunk while computing
            issue_chunk(gb4 + (size_t)(c + 1) * (CH * GW / 4),
                        sbase[(c + 1) & 1], lane);

        const float* sbuf = &sm[w][c & 1][0];

        #pragma unroll
        for (int r = 0; r < CH; ++r) {
            if (c == 0 && r == 0) continue;     // t=0 consumed by init
            const float* srow = sbuf + r * GW;
            float p[5];
            #pragma unroll
            for (int i = 0; i < 5; ++i) p[i] = valid[i] ? srow[eidx[i]] : 0.0f;

            float q4 = __shfl_up_sync(0xffffffffu, a[4], 1);   // state 5*lane-1
            float q3 = __shfl_up_sync(0xffffffffu, a[3], 1);   // state 5*lane-2
            if (lane == 0) { q4 = 0.0f; q3 = 0.0f; }

            float n0 = (a[0] + q4   + skipm[0] * q3  ) * p[0];
            float n1 = (a[1] + a[0] + skipm[1] * q4  ) * p[1];
            float n2 = (a[2] + a[1] + skipm[2] * a[0]) * p[2];
            float n3 = (a[3] + a[2] + skipm[3] * a[1]) * p[3];
            float n4 = (a[4] + a[3] + skipm[4] * a[2]) * p[4];
            a[0] = n0; a[1] = n1; a[2] = n2; a[3] = n3; a[4] = n4;

            if ((r & 7) == 7) {                 // renormalize every 8 steps
                float m = fmaxf(fmaxf(fmaxf(a[0], a[1]), fmaxf(a[2], a[3])), a[4]);
                #pragma unroll
                for (int o = 16; o; o >>= 1)
                    m = fmaxf(m, __shfl_xor_sync(0xffffffffu, m, o));
                // k = unbiased exponent of m; scale = 2^-k (pure bit ops)
                int ebits = (__float_as_int(m) >> 23) & 0xFF;
                float scale = __int_as_float((254 - ebits) << 23);
                acc += (float)(ebits - 127);
                #pragma unroll
                for (int i = 0; i < 5; ++i) a[i] *= scale;
            }
        }

        if (c + 1 < NCHUNK) wait_cp();          // next buffer ready
    }

    // states 127 (i=2) and 128 (i=3) live in lane 25
    if (lane == 25) {
        float s = a[2] + a[3];                  // tail sum, linear
        out[b] = -(flog2(s) + acc) * LN2F;
    }
}

// ---------------------------------------------------------------------------
extern "C" void kernel_launch(void* const* d_in, const int* in_sizes, int n_in,
                              void* d_out, int out_size) {
    // y_pred is by far the larger buffer; robust to metadata ordering.
    const float* yp;
    const int*   yt;
    if (in_sizes[0] > in_sizes[1]) {
        yp = (const float*)d_in[0];
        yt = (const int*)d_in[1];
    } else {
        yp = (const float*)d_in[1];
        yt = (const int*)d_in[0];
    }
    float* out = (float*)d_out;

    k_reduce_gather<<<(BB * TT) / 8, 256>>>(yp, yt);   // one warp per (b,t) row
    k_alpha<<<BB / 4, 128>>>(yt, out);                 // one warp per batch
}